// round 10
// baseline (speedup 1.0000x reference)
#include <cuda_runtime.h>
#include <cstdint>

// out[n,m,:4] = relu( zw4[n] + xwb4[m] ),  zw4 = z@W1, xwb4 = x^T@W2 + b
// N=8192, M=128, DZ=DX=128, H=4.
//
// ONE kernel, 256 blocks x 256 threads, NO cross-block sync:
//  - zw: block-local (32 rows, warp does 4 rows, ILP'd butterfly reduce)
//  - xwb: redundantly computed per block (parallel 8-warp d-split; at 256
//    blocks the chip-wide cost is ~1us; x/W are L1/L2-resident)
//  - output tile (32x128 float4 = 64KB) built in SMEM, then drained with
//    cp.async.bulk (TMA store) -> bypasses the STG issue path that pinned
//    the streaming phase at ~6.3us in rounds 5-8.

#define N_ROWS   8192
#define M_COLS   128
#define D_Z      128
#define D_X      128
#define NBLOCKS  256
#define NTHREADS 256
#define ROWS_PB  (N_ROWS / NBLOCKS)          // 32
#define TILE_F4  (ROWS_PB * M_COLS)          // 4096 float4 = 64 KB
#define SMEM_F4  (TILE_F4 + M_COLS + ROWS_PB)
#define SMEM_BYTES (SMEM_F4 * 16)            // 68,096 B dynamic smem

__global__ __launch_bounds__(NTHREADS)
void fused_tma_kernel(const float* __restrict__ z,
                      const float* __restrict__ x,
                      const float* __restrict__ W,
                      const float* __restrict__ b,
                      float4* __restrict__ out4)
{
    extern __shared__ float4 smem[];
    float4* tile = smem;                     // [4096]  (64 KB)
    float4* sXWB = smem + TILE_F4;           // [128]
    float4* sZW  = smem + TILE_F4 + M_COLS;  // [32]
    // xwb partials alias the tile region (dead until after the reduce barrier)
    float4 (*sPart)[M_COLS] = reinterpret_cast<float4(*)[M_COLS]>(smem);

    const int tid  = threadIdx.x;
    const int bid  = blockIdx.x;
    const int lane = tid & 31;
    const int warp = tid >> 5;
    const float4* W4 = reinterpret_cast<const float4*>(W);

    // ---- Phase Z: zw for rows [bid*32, bid*32+32); warp does 4 rows, ILP'd ----
    const int n0 = bid * ROWS_PB + warp * 4;
    {
        const float4 w0 = W4[lane * 4 + 0];          // W1 rows, L1 broadcast
        const float4 w1 = W4[lane * 4 + 1];
        const float4 w2 = W4[lane * 4 + 2];
        const float4 w3 = W4[lane * 4 + 3];

        float4 acc[4];
        #pragma unroll
        for (int r = 0; r < 4; ++r) {
            const float4 zv = reinterpret_cast<const float4*>(
                                  z + (size_t)(n0 + r) * D_Z)[lane];  // coalesced
            float4 a;
            a.x = zv.x * w0.x; a.y = zv.x * w0.y; a.z = zv.x * w0.z; a.w = zv.x * w0.w;
            a.x = fmaf(zv.y, w1.x, a.x); a.y = fmaf(zv.y, w1.y, a.y);
            a.z = fmaf(zv.y, w1.z, a.z); a.w = fmaf(zv.y, w1.w, a.w);
            a.x = fmaf(zv.z, w2.x, a.x); a.y = fmaf(zv.z, w2.y, a.y);
            a.z = fmaf(zv.z, w2.z, a.z); a.w = fmaf(zv.z, w2.w, a.w);
            a.x = fmaf(zv.w, w3.x, a.x); a.y = fmaf(zv.w, w3.y, a.y);
            a.z = fmaf(zv.w, w3.z, a.z); a.w = fmaf(zv.w, w3.w, a.w);
            acc[r] = a;
        }
        #pragma unroll
        for (int off = 16; off; off >>= 1) {         // 16 indep chains: ILP
            #pragma unroll
            for (int r = 0; r < 4; ++r) {
                acc[r].x += __shfl_xor_sync(0xffffffffu, acc[r].x, off);
                acc[r].y += __shfl_xor_sync(0xffffffffu, acc[r].y, off);
                acc[r].z += __shfl_xor_sync(0xffffffffu, acc[r].z, off);
                acc[r].w += __shfl_xor_sync(0xffffffffu, acc[r].w, off);
            }
        }
        if (lane < 4) sZW[warp * 4 + lane] = acc[lane];
    }

    // ---- Phase X: xwb partials. Warp w owns d in [16w,16w+16);
    //      lane covers m = 4*lane..4*lane+3 via float4 x loads. ----
    {
        const float4* x4 = reinterpret_cast<const float4*>(x);
        float4 acc[4] = {{0,0,0,0},{0,0,0,0},{0,0,0,0},{0,0,0,0}};
        const int d0 = warp * 16;
        #pragma unroll
        for (int i = 0; i < 16; ++i) {
            const int d = d0 + i;
            const float4 xv = x4[d * 32 + lane];     // L1/L2-resident, coalesced
            const float4 w  = W4[D_Z + d];           // L1 broadcast
            acc[0].x = fmaf(xv.x, w.x, acc[0].x); acc[0].y = fmaf(xv.x, w.y, acc[0].y);
            acc[0].z = fmaf(xv.x, w.z, acc[0].z); acc[0].w = fmaf(xv.x, w.w, acc[0].w);
            acc[1].x = fmaf(xv.y, w.x, acc[1].x); acc[1].y = fmaf(xv.y, w.y, acc[1].y);
            acc[1].z = fmaf(xv.y, w.z, acc[1].z); acc[1].w = fmaf(xv.y, w.w, acc[1].w);
            acc[2].x = fmaf(xv.z, w.x, acc[2].x); acc[2].y = fmaf(xv.z, w.y, acc[2].y);
            acc[2].z = fmaf(xv.z, w.z, acc[2].z); acc[2].w = fmaf(xv.z, w.w, acc[2].w);
            acc[3].x = fmaf(xv.w, w.x, acc[3].x); acc[3].y = fmaf(xv.w, w.y, acc[3].y);
            acc[3].z = fmaf(xv.w, w.z, acc[3].z); acc[3].w = fmaf(xv.w, w.w, acc[3].w);
        }
        #pragma unroll
        for (int c = 0; c < 4; ++c) sPart[warp][lane * 4 + c] = acc[c];
    }
    __syncthreads();

    if (tid < M_COLS) {
        float4 s = *reinterpret_cast<const float4*>(b);
        #pragma unroll
        for (int w = 0; w < 8; ++w) {
            const float4 p = sPart[w][tid];
            s.x += p.x; s.y += p.y; s.z += p.z; s.w += p.w;
        }
        sXWB[tid] = s;
    }
    __syncthreads();   // sPart dead from here; tile region reusable

    // ---- Build output tile in SMEM: 16 float4 per thread, conflict-free ----
    #pragma unroll
    for (int it = 0; it < 16; ++it) {
        const int i  = it * NTHREADS + tid;   // 0..4095
        const int nl = i >> 7;                // local row (warp-uniform)
        const int m  = i & 127;
        const float4 a = sZW[nl];
        const float4 c = sXWB[m];
        float4 r;
        r.x = fmaxf(a.x + c.x, 0.f);
        r.y = fmaxf(a.y + c.y, 0.f);
        r.z = fmaxf(a.z + c.z, 0.f);
        r.w = fmaxf(a.w + c.w, 0.f);
        tile[i] = r;                          // STS.128, conflict-free
    }

    // ---- Drain tile via TMA bulk stores (bypasses STG issue path) ----
    asm volatile("fence.proxy.async.shared::cta;" ::: "memory");
    __syncthreads();

    if (tid == 0) {
        const uint64_t gbase = (uint64_t)(out4 + (size_t)bid * TILE_F4);
        uint32_t sbase;
        asm("{ .reg .u64 t; cvta.to.shared.u64 t, %1; cvt.u32.u64 %0, t; }"
            : "=r"(sbase) : "l"(tile));
        #pragma unroll
        for (int c = 0; c < 4; ++c) {         // 4 x 16 KB chunks
            asm volatile(
                "cp.async.bulk.global.shared::cta.bulk_group [%0], [%1], %2;"
                :: "l"(gbase + (uint64_t)c * 16384),
                   "r"(sbase + c * 16384),
                   "r"(16384)
                : "memory");
        }
        asm volatile("cp.async.bulk.commit_group;" ::: "memory");
        asm volatile("cp.async.bulk.wait_group 0;" ::: "memory");
    }
}

extern "C" void kernel_launch(void* const* d_in, const int* in_sizes, int n_in,
                              void* d_out, int out_size)
{
    const float* z = (const float*)d_in[0];   // [8192,128]
    const float* x = (const float*)d_in[1];   // [128,128]
    const float* W = (const float*)d_in[2];   // [256,4]
    const float* b = (const float*)d_in[3];   // [4]
    float4* out4   = (float4*)d_out;

    static bool attr_done = false;
    if (!attr_done) {
        cudaFuncSetAttribute(fused_tma_kernel,
                             cudaFuncAttributeMaxDynamicSharedMemorySize,
                             SMEM_BYTES);
        attr_done = true;
    }
    fused_tma_kernel<<<NBLOCKS, NTHREADS, SMEM_BYTES>>>(z, x, W, b, out4);
}

// round 11
// speedup vs baseline: 1.2149x; 1.2149x over previous
#include <cuda_runtime.h>

// out[n,m,:4] = relu( zw4[n] + xwb4[m] ),  zw4 = z@W1, xwb4 = x^T@W2 + b
// N=8192, M=128, DZ=DX=128, H=4.
//
// ONE kernel, 128 blocks x 512 threads, 64 rows per block, direct STG:
//  - z loads issued first (DRAM), xwb redundant compute overlaps them
//  - xwb: 16-warp d-split (8 d each) -> 128 FFMA/thread; at 128 blocks the
//    chip-wide redundancy is ~0.45us (R7's failure was 512 blocks x 2x work)
//  - zw: block-local, 4 rows/warp, ILP'd butterfly reduce
//  - stream: 16 coalesced STG.128 per thread from 2 small shared tables

#define N_ROWS   8192
#define M_COLS   128
#define D_Z      128
#define D_X      128
#define NBLOCKS  128
#define NTHREADS 512
#define NWARPS   (NTHREADS / 32)       // 16
#define ROWS_PB  (N_ROWS / NBLOCKS)    // 64
#define TILE_F4  (ROWS_PB * M_COLS)    // 8192 float4 per block

__global__ __launch_bounds__(NTHREADS)
void fused_kernel(const float* __restrict__ z,
                  const float* __restrict__ x,
                  const float* __restrict__ W,
                  const float* __restrict__ b,
                  float4* __restrict__ out4)
{
    __shared__ float4 sPart[NWARPS][M_COLS];   // 32 KB xwb partials
    __shared__ float4 sXWB[M_COLS];            // 2 KB
    __shared__ float4 sZW[ROWS_PB];            // 1 KB

    const int tid  = threadIdx.x;
    const int bid  = blockIdx.x;
    const int lane = tid & 31;
    const int warp = tid >> 5;                 // 0..15
    const float4* W4 = reinterpret_cast<const float4*>(W);
    const float4* x4 = reinterpret_cast<const float4*>(x);

    // ---- 1) Issue z loads early (DRAM, MLP=4): warp owns rows n0..n0+3 ----
    const int n0 = bid * ROWS_PB + warp * 4;
    float4 zv[4];
    #pragma unroll
    for (int r = 0; r < 4; ++r)
        zv[r] = reinterpret_cast<const float4*>(
                    z + (size_t)(n0 + r) * D_Z)[lane];       // coalesced 512B

    // ---- 2) xwb partials while z is in flight.
    //      Warp w owns d in [8w, 8w+8); lane covers m = 4*lane..4*lane+3. ----
    {
        float4 acc[4] = {{0,0,0,0},{0,0,0,0},{0,0,0,0},{0,0,0,0}};
        const int d0 = warp * 8;
        #pragma unroll
        for (int i = 0; i < 8; ++i) {
            const int d = d0 + i;
            const float4 xv = x4[d * 32 + lane];             // L2-resident
            const float4 w  = W4[D_Z + d];                   // L1 broadcast
            acc[0].x = fmaf(xv.x, w.x, acc[0].x); acc[0].y = fmaf(xv.x, w.y, acc[0].y);
            acc[0].z = fmaf(xv.x, w.z, acc[0].z); acc[0].w = fmaf(xv.x, w.w, acc[0].w);
            acc[1].x = fmaf(xv.y, w.x, acc[1].x); acc[1].y = fmaf(xv.y, w.y, acc[1].y);
            acc[1].z = fmaf(xv.y, w.z, acc[1].z); acc[1].w = fmaf(xv.y, w.w, acc[1].w);
            acc[2].x = fmaf(xv.z, w.x, acc[2].x); acc[2].y = fmaf(xv.z, w.y, acc[2].y);
            acc[2].z = fmaf(xv.z, w.z, acc[2].z); acc[2].w = fmaf(xv.z, w.w, acc[2].w);
            acc[3].x = fmaf(xv.w, w.x, acc[3].x); acc[3].y = fmaf(xv.w, w.y, acc[3].y);
            acc[3].z = fmaf(xv.w, w.z, acc[3].z); acc[3].w = fmaf(xv.w, w.w, acc[3].w);
        }
        #pragma unroll
        for (int c = 0; c < 4; ++c) sPart[warp][lane * 4 + c] = acc[c];
    }

    // ---- 3) zw for this warp's 4 rows (z now arrived), ILP'd reduce ----
    {
        const float4 w0 = W4[lane * 4 + 0];
        const float4 w1 = W4[lane * 4 + 1];
        const float4 w2 = W4[lane * 4 + 2];
        const float4 w3 = W4[lane * 4 + 3];

        float4 acc[4];
        #pragma unroll
        for (int r = 0; r < 4; ++r) {
            float4 a;
            a.x = zv[r].x * w0.x; a.y = zv[r].x * w0.y;
            a.z = zv[r].x * w0.z; a.w = zv[r].x * w0.w;
            a.x = fmaf(zv[r].y, w1.x, a.x); a.y = fmaf(zv[r].y, w1.y, a.y);
            a.z = fmaf(zv[r].y, w1.z, a.z); a.w = fmaf(zv[r].y, w1.w, a.w);
            a.x = fmaf(zv[r].z, w2.x, a.x); a.y = fmaf(zv[r].z, w2.y, a.y);
            a.z = fmaf(zv[r].z, w2.z, a.z); a.w = fmaf(zv[r].z, w2.w, a.w);
            a.x = fmaf(zv[r].w, w3.x, a.x); a.y = fmaf(zv[r].w, w3.y, a.y);
            a.z = fmaf(zv[r].w, w3.z, a.z); a.w = fmaf(zv[r].w, w3.w, a.w);
            acc[r] = a;
        }
        #pragma unroll
        for (int off = 16; off; off >>= 1) {   // 16 independent chains: ILP
            #pragma unroll
            for (int r = 0; r < 4; ++r) {
                acc[r].x += __shfl_xor_sync(0xffffffffu, acc[r].x, off);
                acc[r].y += __shfl_xor_sync(0xffffffffu, acc[r].y, off);
                acc[r].z += __shfl_xor_sync(0xffffffffu, acc[r].z, off);
                acc[r].w += __shfl_xor_sync(0xffffffffu, acc[r].w, off);
            }
        }
        if (lane < 4) sZW[warp * 4 + lane] = acc[lane];
    }
    __syncthreads();

    // ---- 4) Fold xwb partials: 128 threads, 16-way add + bias ----
    if (tid < M_COLS) {
        float4 s = *reinterpret_cast<const float4*>(b);
        #pragma unroll
        for (int w = 0; w < NWARPS; ++w) {
            const float4 p = sPart[w][tid];
            s.x += p.x; s.y += p.y; s.z += p.z; s.w += p.w;
        }
        sXWB[tid] = s;
    }
    __syncthreads();

    // ---- 5) Stream: 64 rows * 128 m = 8192 float4/block, 16 per thread ----
    const size_t base = (size_t)bid * TILE_F4;
    #pragma unroll
    for (int it = 0; it < 16; ++it) {
        const int i  = it * NTHREADS + tid;    // 0..8191
        const int nl = i >> 7;                 // local row: warp-uniform
        const int m  = i & 127;                // conflict-free LDS.128
        const float4 a = sZW[nl];
        const float4 c = sXWB[m];
        float4 r;
        r.x = fmaxf(a.x + c.x, 0.f);
        r.y = fmaxf(a.y + c.y, 0.f);
        r.z = fmaxf(a.z + c.z, 0.f);
        r.w = fmaxf(a.w + c.w, 0.f);
        out4[base + i] = r;                    // fully coalesced STG.128
    }
}

extern "C" void kernel_launch(void* const* d_in, const int* in_sizes, int n_in,
                              void* d_out, int out_size)
{
    const float* z = (const float*)d_in[0];   // [8192,128]
    const float* x = (const float*)d_in[1];   // [128,128]
    const float* W = (const float*)d_in[2];   // [256,4]
    const float* b = (const float*)d_in[3];   // [4]
    float4* out4   = (float4*)d_out;

    fused_kernel<<<NBLOCKS, NTHREADS>>>(z, x, W, b, out4);
}